// round 7
// baseline (speedup 1.0000x reference)
#include <cuda_runtime.h>
#include <math.h>

#define BN 16384
#define NCS 64
#define NFS 128
#define NTOT 192
#define H 64
#define TP 128          // points per block
#define MTHREADS 256

typedef unsigned long long u64;

// ---------------- scratch ----------------
__device__ float4 g_rgbd_c[BN * NCS];
__device__ float4 g_rgbd_f[BN * NTOT];
__device__ float  g_zt[NTOT * BN];       // fine z_vals transposed: z[j*BN + b]

__device__ __forceinline__ float tval_of(float nb, float fb, int i) {
    float tt = (float)i * (1.0f / 63.0f);
    return nb * (1.0f - tt) + fb * tt;
}

// ---- f32x2 packed helpers ----
__device__ __forceinline__ u64 pk2(float lo, float hi) {
    u64 r; asm("mov.b64 %0, {%1, %2};" : "=l"(r) : "f"(lo), "f"(hi)); return r;
}
__device__ __forceinline__ void upk2(u64 v, float& lo, float& hi) {
    asm("mov.b64 {%0, %1}, %2;" : "=f"(lo), "=f"(hi) : "l"(v));
}
__device__ __forceinline__ u64 ffma2(u64 a, u64 b, u64 c) {
    u64 d; asm("fma.rn.f32x2 %0, %1, %2, %3;" : "=l"(d) : "l"(a), "l"(b), "l"(c)); return d;
}
__device__ __forceinline__ u64 relu2(u64 v) {
    float a, b; upk2(v, a, b);
    return pk2(fmaxf(a, 0.0f), fmaxf(b, 0.0f));
}

// ------------- blocked MLP: 128 points per block, 256 threads -------------
// Layer1 staged to SMEM; layer2 as register-blocked GEMM (4 pts x 8 units per
// thread, f32x2 accumulators); head layer via 8-lane shuffle reduction.
__global__ __launch_bounds__(MTHREADS) void mlp_gemm_kernel(
    const float* __restrict__ origins, const float* __restrict__ dirs,
    const float* __restrict__ nearp,   const float* __restrict__ farp,
    const float* __restrict__ w1, const float* __restrict__ b1,
    const float* __restrict__ w2, const float* __restrict__ b2,
    const float* __restrict__ wr, const float* __restrict__ br,
    const float* __restrict__ wd, const float* __restrict__ bd,
    int use_z, float4* __restrict__ out_rgbd)
{
    __shared__ float s_h1[H * TP];        // 32KB: s_h1[k*TP + p]
    __shared__ u64   s_w2p[H * 32];       // 16KB: (w2[k][2jp], w2[k][2jp+1])
    __shared__ u64   s_hd[32 * 4];        // head: (hw[c][2jp], hw[c][2jp+1]), hw3=wd
    __shared__ u64   s_b2p[32];
    __shared__ float s_w1[3 * H], s_b1[H], s_hb[4];

    int tid = threadIdx.x;

    for (int i = tid; i < H * 32; i += MTHREADS) {
        int k = i >> 5, jp = i & 31;
        s_w2p[i] = pk2(w2[k * H + 2 * jp], w2[k * H + 2 * jp + 1]);
    }
    for (int i = tid; i < 128; i += MTHREADS) {
        int jp = i >> 2, c = i & 3;
        float v0 = (c < 3) ? wr[(2 * jp) * 3 + c]     : wd[2 * jp];
        float v1 = (c < 3) ? wr[(2 * jp + 1) * 3 + c] : wd[2 * jp + 1];
        s_hd[jp * 4 + c] = pk2(v0, v1);
    }
    if (tid < 32) s_b2p[tid] = pk2(b2[2 * tid], b2[2 * tid + 1]);
    for (int i = tid; i < H; i += MTHREADS) {
        s_w1[i] = w1[i]; s_w1[H + i] = w1[H + i]; s_w1[2 * H + i] = w1[2 * H + i];
        s_b1[i] = b1[i];
    }
    if (tid < 3) s_hb[tid] = br[tid];
    if (tid == 3) s_hb[3] = bd[0];
    __syncthreads();

    unsigned base = blockIdx.x * TP;

    // ---- phase 1: layer-1 into SMEM. thread (p = tid&127, half = tid>>7) ----
    {
        int p = tid & (TP - 1);
        int half = tid >> 7;
        unsigned pf = base + p;
        int b = (int)(pf & (BN - 1));
        int j = (int)(pf >> 14);
        float t;
        if (use_z) t = g_zt[pf];
        else       t = tval_of(nearp[b], farp[b], j);
        float x = origins[3 * b]     + t * dirs[3 * b];
        float y = origins[3 * b + 1] + t * dirs[3 * b + 1];
        float z = origins[3 * b + 2] + t * dirs[3 * b + 2];
        int k0 = half * 32;
        #pragma unroll
        for (int kk = 0; kk < 32; kk++) {
            int k = k0 + kk;
            float v = s_b1[k] + x * s_w1[k] + y * s_w1[H + k] + z * s_w1[2 * H + k];
            s_h1[k * TP + p] = fmaxf(v, 0.0f);
        }
    }
    __syncthreads();

    // ---- phase 2: layer-2 GEMM. thread tile: 4 points x 4 jj-pairs ----
    int pg = tid >> 3;      // 0..31 : point group (4 points)
    int jg = tid & 7;       // 0..7  : jj group (4 pairs = 8 units)

    u64 acc[4][4];
    #pragma unroll
    for (int pi = 0; pi < 4; pi++)
        #pragma unroll
        for (int jp = 0; jp < 4; jp++)
            acc[pi][jp] = s_b2p[jg * 4 + jp];

    #pragma unroll 8
    for (int k = 0; k < H; k++) {
        float4 hq = *reinterpret_cast<const float4*>(&s_h1[k * TP + pg * 4]);
        u64 h0 = pk2(hq.x, hq.x);
        u64 h1v = pk2(hq.y, hq.y);
        u64 h2v = pk2(hq.z, hq.z);
        u64 h3 = pk2(hq.w, hq.w);
        ulonglong2 wA = *reinterpret_cast<const ulonglong2*>(&s_w2p[k * 32 + jg * 4]);
        ulonglong2 wB = *reinterpret_cast<const ulonglong2*>(&s_w2p[k * 32 + jg * 4 + 2]);
        acc[0][0] = ffma2(h0, wA.x, acc[0][0]);
        acc[0][1] = ffma2(h0, wA.y, acc[0][1]);
        acc[0][2] = ffma2(h0, wB.x, acc[0][2]);
        acc[0][3] = ffma2(h0, wB.y, acc[0][3]);
        acc[1][0] = ffma2(h1v, wA.x, acc[1][0]);
        acc[1][1] = ffma2(h1v, wA.y, acc[1][1]);
        acc[1][2] = ffma2(h1v, wB.x, acc[1][2]);
        acc[1][3] = ffma2(h1v, wB.y, acc[1][3]);
        acc[2][0] = ffma2(h2v, wA.x, acc[2][0]);
        acc[2][1] = ffma2(h2v, wA.y, acc[2][1]);
        acc[2][2] = ffma2(h2v, wB.x, acc[2][2]);
        acc[2][3] = ffma2(h2v, wB.y, acc[2][3]);
        acc[3][0] = ffma2(h3, wA.x, acc[3][0]);
        acc[3][1] = ffma2(h3, wA.y, acc[3][1]);
        acc[3][2] = ffma2(h3, wB.x, acc[3][2]);
        acc[3][3] = ffma2(h3, wB.y, acc[3][3]);
    }

    // ---- phase 3: relu + head partials + 8-lane reduce ----
    u64 hd[4][4];   // [jp][c]
    #pragma unroll
    for (int jp = 0; jp < 4; jp++) {
        ulonglong2 d0 = *reinterpret_cast<const ulonglong2*>(&s_hd[(jg * 4 + jp) * 4]);
        ulonglong2 d1 = *reinterpret_cast<const ulonglong2*>(&s_hd[(jg * 4 + jp) * 4 + 2]);
        hd[jp][0] = d0.x; hd[jp][1] = d0.y; hd[jp][2] = d1.x; hd[jp][3] = d1.y;
    }

    float part[4][4];   // [pi][c]
    #pragma unroll
    for (int pi = 0; pi < 4; pi++) {
        u64 p0 = 0, p1 = 0, p2 = 0, p3 = 0;
        #pragma unroll
        for (int jp = 0; jp < 4; jp++) {
            u64 a = relu2(acc[pi][jp]);
            p0 = ffma2(a, hd[jp][0], p0);
            p1 = ffma2(a, hd[jp][1], p1);
            p2 = ffma2(a, hd[jp][2], p2);
            p3 = ffma2(a, hd[jp][3], p3);
        }
        float lo, hi;
        upk2(p0, lo, hi); part[pi][0] = lo + hi;
        upk2(p1, lo, hi); part[pi][1] = lo + hi;
        upk2(p2, lo, hi); part[pi][2] = lo + hi;
        upk2(p3, lo, hi); part[pi][3] = lo + hi;
    }
    // reduce across the 8 jg lanes (lanes pg*8+jg are consecutive in the warp)
    #pragma unroll
    for (int o = 4; o >= 1; o >>= 1) {
        #pragma unroll
        for (int pi = 0; pi < 4; pi++) {
            #pragma unroll
            for (int c = 0; c < 4; c++)
                part[pi][c] += __shfl_xor_sync(0xffffffffu, part[pi][c], o);
        }
    }
    if (jg == 0) {
        float hb0 = s_hb[0], hb1 = s_hb[1], hb2 = s_hb[2], hb3 = s_hb[3];
        #pragma unroll
        for (int pi = 0; pi < 4; pi++) {
            unsigned pf = base + pg * 4 + pi;
            float4 o;
            o.x = 1.f / (1.f + expf(-(part[pi][0] + hb0)));
            o.y = 1.f / (1.f + expf(-(part[pi][1] + hb1)));
            o.z = 1.f / (1.f + expf(-(part[pi][2] + hb2)));
            o.w = fmaxf(part[pi][3] + hb3, 0.f);
            out_rgbd[pf] = o;
        }
    }
}

// ---------------- coarse render + inverse-CDF + merge : one thread per ray (verified) ----------------
__global__ __launch_bounds__(128) void render_coarse_kernel(
    const float* __restrict__ origins, const float* __restrict__ dirs,
    const float* __restrict__ nearp,   const float* __restrict__ farp,
    const float* __restrict__ bkgd,
    float* __restrict__ out)
{
    int b = blockIdx.x * blockDim.x + threadIdx.x;
    if (b >= BN) return;

    float nb = nearp[b], fb = farp[b];
    float n0 = nearp[0], f0 = farp[0];
    float dx = dirs[3 * b], dy = dirs[3 * b + 1], dz = dirs[3 * b + 2];
    float dn = sqrtf(dx * dx + dy * dy + dz * dz);

    float w[NCS];
    float T = 0.f, c0 = 0.f, c1 = 0.f, c2 = 0.f, acc = 0.f, depth = 0.f, s0 = 0.f;
    for (int j = 0; j < NCS; j++) {
        float tj  = tval_of(nb, fb, j);
        float tdist = (j < NCS - 1) ? (tval_of(nb, fb, j + 1) - tj) : 1e10f;
        float4 rd = g_rgbd_c[j * BN + b];
        float dd = rd.w * tdist * dn;
        float alpha = 1.0f - expf(-dd);
        float trans = expf(-T);
        float wj = alpha * trans;
        T += dd;
        w[j] = wj;
        c0 += wj * rd.x; c1 += wj * rd.y; c2 += wj * rd.z;
        acc += wj;
        depth += wj * tj;
        s0 += wj * tval_of(n0, f0, j);
    }
    c0 += bkgd[0] * (1.0f - acc);
    c1 += bkgd[1] * (1.0f - acc);
    c2 += bkgd[2] * (1.0f - acc);

    float o0x = origins[0], o0y = origins[1], o0z = origins[2];
    float d0x = dirs[0],    d0y = dirs[1],    d0z = dirs[2];
    float* po = out + (size_t)b * 16;
    po[0] = c0; po[1] = c1; po[2] = c2;
    po[3] = depth; po[4] = acc;
    po[5] = acc * o0x + s0 * d0x;
    po[6] = acc * o0y + s0 * d0y;
    po[7] = acc * o0z + s0 * d0z;

    // ---- piecewise-constant PDF inverse-CDF sampling ----
    float ws = 0.f;
    for (int i = 0; i < 62; i++) ws += w[i + 1];
    float pad  = fmaxf(1e-5f - ws, 0.f);
    float padd = pad * (1.0f / 62.0f);
    ws += pad;
    float inv_ws = 1.0f / ws;

    float cdf[63];
    cdf[0] = 0.f;
    float run = 0.f;
    for (int i = 1; i <= 61; i++) {
        run += (w[i] + padd) * inv_ws;
        cdf[i] = fminf(run, 1.f);
    }
    cdf[62] = 1.f;

    const float F32EPS = 1.1920928955078125e-7f;
    const float ustep = (1.0f - F32EPS) * (1.0f / 127.0f);
    int i0 = 0;
    int ti = 0;
    int outn = 0;
    for (int s = 0; s < NFS; s++) {
        float u = (float)s * ustep;
        while (i0 + 1 < 62 + 1 && cdf[i0 + 1] <= u) i0++;
        float cg0 = cdf[i0], cg1 = cdf[i0 + 1];
        float bg0 = 0.5f * (tval_of(nb, fb, i0)     + tval_of(nb, fb, i0 + 1));
        float bg1 = 0.5f * (tval_of(nb, fb, i0 + 1) + tval_of(nb, fb, i0 + 2));
        float denom = cg1 - cg0;
        float tf = (denom > 0.f) ? (u - cg0) / denom : 0.f;
        tf = fminf(fmaxf(tf, 0.f), 1.f);
        float zs = bg0 + tf * (bg1 - bg0);
        while (ti < NCS && tval_of(nb, fb, ti) <= zs) {
            g_zt[outn * BN + b] = tval_of(nb, fb, ti);
            outn++; ti++;
        }
        g_zt[outn * BN + b] = zs;
        outn++;
    }
    while (ti < NCS) {
        g_zt[outn * BN + b] = tval_of(nb, fb, ti);
        outn++; ti++;
    }
}

// ---------------- fine render : one thread per ray (verified) ----------------
__global__ __launch_bounds__(128) void render_fine_kernel(
    const float* __restrict__ origins, const float* __restrict__ dirs,
    const float* __restrict__ bkgd,
    float* __restrict__ out)
{
    int b = blockIdx.x * blockDim.x + threadIdx.x;
    if (b >= BN) return;

    float dx = dirs[3 * b], dy = dirs[3 * b + 1], dz = dirs[3 * b + 2];
    float dn = sqrtf(dx * dx + dy * dy + dz * dz);

    float T = 0.f, c0 = 0.f, c1 = 0.f, c2 = 0.f, acc = 0.f, depth = 0.f, s1 = 0.f;
    float zj = g_zt[b];
    for (int j = 0; j < NTOT; j++) {
        float zj1 = (j < NTOT - 1) ? g_zt[(j + 1) * BN + b] : 0.f;
        float tdist = (j < NTOT - 1) ? (zj1 - zj) : 1e10f;
        float4 rd = g_rgbd_f[j * BN + b];
        float dd = rd.w * tdist * dn;
        float alpha = 1.0f - expf(-dd);
        float wj = alpha * expf(-T);
        T += dd;
        c0 += wj * rd.x; c1 += wj * rd.y; c2 += wj * rd.z;
        acc += wj;
        depth += wj * zj;
        s1 += wj * g_zt[j * BN];
        zj = zj1;
    }
    c0 += bkgd[0] * (1.0f - acc);
    c1 += bkgd[1] * (1.0f - acc);
    c2 += bkgd[2] * (1.0f - acc);

    float o0x = origins[0], o0y = origins[1], o0z = origins[2];
    float d0x = dirs[0],    d0y = dirs[1],    d0z = dirs[2];
    float* po = out + (size_t)b * 16;
    po[8]  = c0; po[9] = c1; po[10] = c2;
    po[11] = depth; po[12] = acc;
    po[13] = acc * o0x + s1 * d0x;
    po[14] = acc * o0y + s1 * d0y;
    po[15] = acc * o0z + s1 * d0z;
}

// ---------------- launch ----------------
extern "C" void kernel_launch(void* const* d_in, const int* in_sizes, int n_in,
                              void* d_out, int out_size)
{
    const float* origins = (const float*)d_in[0];
    const float* dirs    = (const float*)d_in[1];
    const float* nearp   = (const float*)d_in[2];
    const float* farp    = (const float*)d_in[3];
    const float* bkgd    = (const float*)d_in[4];
    const float* w1_c = (const float*)d_in[5];
    const float* b1_c = (const float*)d_in[6];
    const float* w2_c = (const float*)d_in[7];
    const float* b2_c = (const float*)d_in[8];
    const float* wr_c = (const float*)d_in[9];
    const float* br_c = (const float*)d_in[10];
    const float* wd_c = (const float*)d_in[11];
    const float* bd_c = (const float*)d_in[12];
    const float* w1_f = (const float*)d_in[13];
    const float* b1_f = (const float*)d_in[14];
    const float* w2_f = (const float*)d_in[15];
    const float* b2_f = (const float*)d_in[16];
    const float* wr_f = (const float*)d_in[17];
    const float* br_f = (const float*)d_in[18];
    const float* wd_f = (const float*)d_in[19];
    const float* bd_f = (const float*)d_in[20];
    float* out = (float*)d_out;

    float4* rgbd_c;
    float4* rgbd_f;
    cudaGetSymbolAddress((void**)&rgbd_c, g_rgbd_c);
    cudaGetSymbolAddress((void**)&rgbd_f, g_rgbd_f);

    // 1) coarse MLP: 64*BN points, 128 per block
    mlp_gemm_kernel<<<NCS * BN / TP, MTHREADS>>>(origins, dirs, nearp, farp,
                                                 w1_c, b1_c, w2_c, b2_c, wr_c, br_c, wd_c, bd_c,
                                                 0, rgbd_c);
    // 2) coarse render + PDF sample + stream merge
    render_coarse_kernel<<<BN / 128, 128>>>(origins, dirs, nearp, farp, bkgd, out);
    // 3) fine MLP: 192*BN points
    mlp_gemm_kernel<<<NTOT * BN / TP, MTHREADS>>>(origins, dirs, nearp, farp,
                                                  w1_f, b1_f, w2_f, b2_f, wr_f, br_f, wd_f, bd_f,
                                                  1, rgbd_f);
    // 4) fine render
    render_fine_kernel<<<BN / 128, 128>>>(origins, dirs, bkgd, out);
}